// round 7
// baseline (speedup 1.0000x reference)
#include <cuda_runtime.h>
#include <cuda_fp16.h>
#include <cstdint>

// ===========================================================================
// SNN (20 steps, 2 fused Linear+LIF + feedback), hybrid tensor+SIMT kernel.
// Warps 0-7: HMMA 2-limb fp16 over K [0,Kt).  Warps 8-15: fp32 FFMA GEMM
// over K [Kt,K) using original fp32 weights. Partials combined in smem,
// fused LIF epilogue. Both pipes run concurrently on every SM.
// ===========================================================================

#define BATCH   4096
#define DIM_D   1024
#define DIM_H1  2048
#define DIM_H2  1024
#define DIM_C   64
#define NUM_STEPS 20
#define BETA 0.9f
#define THRV 1.0f

// ---------------------------------------------------------------------------
// Device-global state / scratch
// ---------------------------------------------------------------------------
__device__ float  g_m1 [(size_t)BATCH * DIM_H1];
__device__ float  g_m2 [(size_t)BATCH * DIM_H2];
__device__ float  g_spk[(size_t)BATCH * DIM_H2];
__device__ __half g_s1 [(size_t)BATCH * DIM_H1];
__device__ __half g_s2 [(size_t)BATCH * DIM_H2];
__device__ __half g_w1h [(size_t)DIM_H1 * DIM_D];   // W1 * 2^11, hi limb
__device__ __half g_w1l [(size_t)DIM_H1 * DIM_D];   // W1 * 2^11, lo limb
__device__ __half g_w1hu[(size_t)DIM_H1 * DIM_D];   // W1 hi limb, unscaled (t=0)
__device__ __half g_w2h [(size_t)DIM_H2 * DIM_H1];
__device__ __half g_w2l [(size_t)DIM_H2 * DIM_H1];
__device__ __half g_xh  [(size_t)BATCH * DIM_D];
__device__ __half g_xl  [(size_t)BATCH * DIM_D];
__device__ __half g_xhs [(size_t)BATCH * DIM_D];

// ---------------------------------------------------------------------------
// PTX helpers
// ---------------------------------------------------------------------------
__device__ __forceinline__ uint32_t smem_u32(const void* p) {
    uint32_t a;
    asm("{ .reg .u64 t; cvta.to.shared.u64 t, %1; cvt.u32.u64 %0, t; }"
        : "=r"(a) : "l"(p));
    return a;
}
__device__ __forceinline__ void cp16(uint32_t dst, const void* src) {
    asm volatile("cp.async.cg.shared.global [%0], [%1], 16;"
                 :: "r"(dst), "l"(__cvta_generic_to_global(src)) : "memory");
}
__device__ __forceinline__ void ldsm4(uint32_t addr, uint32_t& r0, uint32_t& r1,
                                      uint32_t& r2, uint32_t& r3) {
    asm volatile("ldmatrix.sync.aligned.m8n8.x4.shared.b16 {%0,%1,%2,%3}, [%4];"
                 : "=r"(r0), "=r"(r1), "=r"(r2), "=r"(r3) : "r"(addr));
}
__device__ __forceinline__ void mma16816(float* c, const uint32_t a[4],
                                         uint32_t b0, uint32_t b1) {
    asm volatile(
        "mma.sync.aligned.m16n8k16.row.col.f32.f16.f16.f32 "
        "{%0,%1,%2,%3}, {%4,%5,%6,%7}, {%8,%9}, {%0,%1,%2,%3};"
        : "+f"(c[0]), "+f"(c[1]), "+f"(c[2]), "+f"(c[3])
        : "r"(a[0]), "r"(a[1]), "r"(a[2]), "r"(a[3]), "r"(b0), "r"(b1));
}
#define BAR1 asm volatile("bar.sync 1, 256;" ::: "memory")
#define BAR2 asm volatile("bar.sync 2, 256;" ::: "memory")

// ===========================================================================
// Hybrid kernel. CTA = 128x128 output tile, 512 threads.
//   warps 0-7 : HMMA, A=spikes(2^-11), W limbs scaled 2^11, K in [0,KT)
//   warps 8-15: fp32 SIMT GEMM, original W (fp32), K in [KT,K)
// ===========================================================================
template <int K, int KT, bool FIRST, bool SUM>
__global__ void __launch_bounds__(512, 1)
snn_hyb(const __half* __restrict__ A, const __half* __restrict__ W0,
        const __half* __restrict__ W1, const float* __restrict__ Wf,
        const float* __restrict__ bias, float* __restrict__ mem,
        __half* __restrict__ spk, float* __restrict__ spk_sum, int N)
{
    constexpr int TILE = 16384;            // 128 rows x 128 B (fp16 K=64 chunk)
    constexpr int TSTAGE = 3 * TILE;       // A + Wh + Wl
    constexpr int NT = KT / 64;
    constexpr int KS = K - KT;
    constexpr int NS = KS / 32;
    constexpr int SBASE = 3 * TSTAGE;      // 147456: SIMT region / partial buf
    constexpr int SSTAGE = 32768;          // A_f32 16K + W_f32 16K

    extern __shared__ char smem[];
    const uint32_t sb = smem_u32(smem);
    const int tid = threadIdx.x, lane = tid & 31, wid = tid >> 5;
    const int brow = blockIdx.y * 128, bcol = blockIdx.x * 128;

    if (wid < 8) {
        // =================== TENSOR GROUP (threads 0-255) ===================
        const int wm = wid >> 2, wn = wid & 3;
        const __half* Ab = A + (size_t)brow * K;
        const __half* Wp[2] = { W0 + (size_t)bcol * K, W1 + (size_t)bcol * K };

        auto load_stage = [&](int st, int k0) {
            const uint32_t s0 = sb + st * TSTAGE;
            for (int q = tid; q < 1024; q += 256) {
                int r = q >> 3, c = q & 7;
                cp16(s0 + r * 128 + ((c ^ (r & 7)) << 4),
                     Ab + (size_t)r * K + k0 + c * 8);
            }
#pragma unroll
            for (int l = 0; l < 2; l++) {
                const __half* g = Wp[l];
                const uint32_t d = s0 + (1 + l) * TILE;
                for (int q = tid; q < 1024; q += 256) {
                    int r = q >> 3, c = q & 7;
                    cp16(d + r * 128 + ((c ^ (r & 7)) << 4),
                         g + (size_t)r * K + k0 + c * 8);
                }
            }
            asm volatile("cp.async.commit_group;" ::: "memory");
        };

        const int arow = (lane & 7) + 8 * ((lane >> 3) & 1);
        const int asel = lane >> 4;
        const int brw  = (lane & 7) + 8 * (lane >> 4);
        const int bsel = (lane >> 3) & 1;
        const int sx   = lane & 7;

        float acc[4][4][4];
#pragma unroll
        for (int i = 0; i < 4; i++)
#pragma unroll
            for (int j = 0; j < 4; j++)
#pragma unroll
                for (int k = 0; k < 4; k++) acc[i][j][k] = 0.0f;

        load_stage(0, 0);
        load_stage(1, 64);

        for (int ch = 0; ch < NT; ch++) {
            if (ch < NT - 1)
                asm volatile("cp.async.wait_group 1;" ::: "memory");
            else
                asm volatile("cp.async.wait_group 0;" ::: "memory");
            BAR1;
            if (ch + 2 < NT) load_stage((ch + 2) % 3, (ch + 2) * 64);

            const uint32_t s0 = sb + (ch % 3) * TSTAGE;
            uint32_t bb[2][2];
#pragma unroll
            for (int w = 0; w < 2; w++)
#pragma unroll
                for (int h = 0; h < 2; h++)
                    bb[w][h] = s0 + (1 + w) * TILE + (wn * 32 + h * 16 + brw) * 128;

#pragma unroll
            for (int ks = 0; ks < 4; ks++) {
                uint32_t b[2][8];
#pragma unroll
                for (int w = 0; w < 2; w++) {
                    const uint32_t off = ((2 * ks + bsel) ^ sx) << 4;
                    ldsm4(bb[w][0] + off, b[w][0], b[w][1], b[w][2], b[w][3]);
                    ldsm4(bb[w][1] + off, b[w][4], b[w][5], b[w][6], b[w][7]);
                }
                const uint32_t aoff = ((2 * ks + asel) ^ sx) << 4;
                uint32_t a[4][4];
#pragma unroll
                for (int mf = 0; mf < 4; mf++)
                    ldsm4(s0 + (wm * 64 + mf * 16 + arow) * 128 + aoff,
                          a[mf][0], a[mf][1], a[mf][2], a[mf][3]);
#pragma unroll
                for (int w = 0; w < 2; w++)
#pragma unroll
                    for (int mf = 0; mf < 4; mf++)
#pragma unroll
                        for (int nf = 0; nf < 4; nf++)
                            mma16816(acc[mf][nf], a[mf], b[w][2 * nf], b[w][2 * nf + 1]);
            }
            BAR1;
        }

        __syncthreads();   // join: SIMT partials now visible

        // ---- Fused LIF epilogue (adds SIMT partial) ----
        const float* part = (const float*)(smem + SBASE);
        const int qr = lane >> 2, qc = (lane & 3) * 2;
#pragma unroll
        for (int mf = 0; mf < 4; mf++)
#pragma unroll
        for (int h = 0; h < 2; h++) {
            const int row_l = wm * 64 + mf * 16 + qr + 8 * h;
            const int row = brow + row_l;
#pragma unroll
            for (int nf = 0; nf < 4; nf++) {
                const int col_l = wn * 32 + nf * 8 + qc;
                const int col = bcol + col_l;
                const size_t ix = (size_t)row * N + col;
                float2 bb2 = *reinterpret_cast<const float2*>(bias + col);
                float2 pp  = *reinterpret_cast<const float2*>(part + row_l * 128 + col_l);
                float v0 = acc[mf][nf][2 * h + 0] + pp.x + bb2.x;
                float v1 = acc[mf][nf][2 * h + 1] + pp.y + bb2.y;
                float m0, m1v;
                if (FIRST) {
                    m0 = v0; m1v = v1;
                } else {
                    float2 mo = *reinterpret_cast<const float2*>(mem + ix);
                    m0  = BETA * mo.x + v0 - ((mo.x > THRV) ? THRV : 0.0f);
                    m1v = BETA * mo.y + v1 - ((mo.y > THRV) ? THRV : 0.0f);
                }
                const bool sp0 = m0 > THRV, sp1 = m1v > THRV;
                *reinterpret_cast<float2*>(mem + ix) = make_float2(m0, m1v);
                uint32_t sv = (sp0 ? 0x1000u : 0u) | (sp1 ? 0x10000000u : 0u);
                *reinterpret_cast<uint32_t*>(spk + ix) = sv;
                if (SUM) {
                    float a0 = sp0 ? 1.0f : 0.0f, a1 = sp1 ? 1.0f : 0.0f;
                    float2* ss = reinterpret_cast<float2*>(spk_sum + ix);
                    if (FIRST) *ss = make_float2(a0, a1);
                    else { float2 o = *ss; *ss = make_float2(o.x + a0, o.y + a1); }
                }
            }
        }
    } else {
        // =================== SIMT GROUP (threads 256-511) ===================
        const int stid = tid - 256;            // 0..255
        const int ws = wid - 8;                // 0..7
        const int cb = ws & 1, rb = ws >> 1;
        const int lr = lane >> 3, lc = lane & 7;
        const int rowb = rb * 32 + lr * 8;     // 8 rows
        const int colb = cb * 64 + lc * 8;     // 8 cols

        const __half* Ag = A + (size_t)brow * K;
        const float*  Wg = Wf + (size_t)bcol * K;

        uint4 ar[2], wr[4];
        auto ldg_chunk = [&](int ch) {
            if (ch >= NS) return;
            const int k0 = KT + ch * 32;
#pragma unroll
            for (int i = 0; i < 2; i++) {
                int q = stid + i * 256, r = q >> 2, sg = q & 3;
                ar[i] = *reinterpret_cast<const uint4*>(Ag + (size_t)r * K + k0 + sg * 8);
            }
#pragma unroll
            for (int i = 0; i < 4; i++) {
                int q = stid + i * 256, c = q >> 3, sg = q & 7;
                wr[i] = *reinterpret_cast<const uint4*>(Wg + (size_t)c * K + k0 + sg * 4);
            }
        };
        auto sts_chunk = [&](int st) {
            char* sA = smem + SBASE + st * SSTAGE;
            char* sW = sA + 16384;
#pragma unroll
            for (int i = 0; i < 2; i++) {
                int q = stid + i * 256, r = q >> 2, sg = q & 3;
                const __half2* h2 = reinterpret_cast<const __half2*>(&ar[i]);
#pragma unroll
                for (int t = 0; t < 4; t++) {
                    float2 f = __half22float2(h2[t]);
                    *reinterpret_cast<float*>(sA + (sg * 8 + 2 * t    ) * 512 + r * 4) = f.x;
                    *reinterpret_cast<float*>(sA + (sg * 8 + 2 * t + 1) * 512 + r * 4) = f.y;
                }
            }
#pragma unroll
            for (int i = 0; i < 4; i++) {
                int q = stid + i * 256, c = q >> 3, sg = q & 7;
                const float* w4 = reinterpret_cast<const float*>(&wr[i]);
#pragma unroll
                for (int t = 0; t < 4; t++)
                    *reinterpret_cast<float*>(sW + (sg * 4 + t) * 512 + c * 4) = w4[t];
            }
        };

        float acc[8][8];
#pragma unroll
        for (int i = 0; i < 8; i++)
#pragma unroll
            for (int j = 0; j < 8; j++) acc[i][j] = 0.0f;

        ldg_chunk(0); sts_chunk(0); ldg_chunk(1);
        BAR2;

        for (int ch = 0; ch < NS; ch++) {
            const char* sA = smem + SBASE + (ch & 1) * SSTAGE;
            const char* sW = sA + 16384;
#pragma unroll 4
            for (int k = 0; k < 32; k++) {
                float4 a0 = *reinterpret_cast<const float4*>(sA + k * 512 + rowb * 4);
                float4 a1 = *reinterpret_cast<const float4*>(sA + k * 512 + rowb * 4 + 16);
                float4 w0 = *reinterpret_cast<const float4*>(sW + k * 512 + colb * 4);
                float4 w1 = *reinterpret_cast<const float4*>(sW + k * 512 + colb * 4 + 16);
                float av[8] = {a0.x, a0.y, a0.z, a0.w, a1.x, a1.y, a1.z, a1.w};
                float wv[8] = {w0.x, w0.y, w0.z, w0.w, w1.x, w1.y, w1.z, w1.w};
#pragma unroll
                for (int i = 0; i < 8; i++)
#pragma unroll
                    for (int j = 0; j < 8; j++)
                        acc[i][j] = fmaf(av[i], wv[j], acc[i][j]);
            }
            if (ch + 1 < NS) { sts_chunk((ch + 1) & 1); ldg_chunk(ch + 2); }
            BAR2;
        }

        // Partial h (scaled back by 2^11: spikes were 2^-11, W was unscaled fp32)
        float* part = reinterpret_cast<float*>(smem + SBASE);
#pragma unroll
        for (int i = 0; i < 8; i++) {
            float4 p0 = make_float4(acc[i][0] * 2048.0f, acc[i][1] * 2048.0f,
                                    acc[i][2] * 2048.0f, acc[i][3] * 2048.0f);
            float4 p1 = make_float4(acc[i][4] * 2048.0f, acc[i][5] * 2048.0f,
                                    acc[i][6] * 2048.0f, acc[i][7] * 2048.0f);
            *reinterpret_cast<float4*>(part + (rowb + i) * 128 + colb)     = p0;
            *reinterpret_cast<float4*>(part + (rowb + i) * 128 + colb + 4) = p1;
        }
        __syncthreads();   // join with tensor group
    }
}

// ===========================================================================
// t=0 layer-1 kernel (real-valued x, 3 fp16 limb products). Runs once.
// ===========================================================================
__global__ void __launch_bounds__(256, 2)
snn_tz(const __half* __restrict__ A0, const __half* __restrict__ A1,
       const __half* __restrict__ A2,
       const __half* __restrict__ W0, const __half* __restrict__ W1,
       const float* __restrict__ bias, float* __restrict__ mem,
       __half* __restrict__ spk, int N, int K)
{
    constexpr int FT = 16384;
    constexpr int FSTAGE = 5 * FT;
    extern __shared__ char smem[];
    const uint32_t sb = smem_u32(smem);

    const int tid = threadIdx.x, lane = tid & 31, wid = tid >> 5;
    const int wm = wid >> 2, wn = wid & 3;
    const int brow = blockIdx.y * 128, bcol = blockIdx.x * 128;

    const __half* Ap[3] = { A0 + (size_t)brow * K, A1 + (size_t)brow * K,
                            A2 + (size_t)brow * K };
    const __half* Wp[2] = { W0 + (size_t)bcol * K, W1 + (size_t)bcol * K };

    auto load_stage = [&](int st, int k0) {
        const uint32_t s0 = sb + st * FSTAGE;
#pragma unroll
        for (int l = 0; l < 3; l++) {
            const uint32_t d = s0 + l * FT;
            for (int q = tid; q < 1024; q += 256) {
                int r = q >> 3, c = q & 7;
                cp16(d + r * 128 + ((c ^ (r & 7)) << 4),
                     Ap[l] + (size_t)r * K + k0 + c * 8);
            }
        }
#pragma unroll
        for (int l = 0; l < 2; l++) {
            const uint32_t d = s0 + (3 + l) * FT;
            for (int q = tid; q < 1024; q += 256) {
                int r = q >> 3, c = q & 7;
                cp16(d + r * 128 + ((c ^ (r & 7)) << 4),
                     Wp[l] + (size_t)r * K + k0 + c * 8);
            }
        }
        asm volatile("cp.async.commit_group;" ::: "memory");
    };

    const int arow = (lane & 7) + 8 * ((lane >> 3) & 1);
    const int asel = lane >> 4;
    const int brw  = (lane & 7) + 8 * (lane >> 4);
    const int bsel = (lane >> 3) & 1;
    const int sx   = lane & 7;

    float acc[4][4][4];
#pragma unroll
    for (int i = 0; i < 4; i++)
#pragma unroll
        for (int j = 0; j < 4; j++)
#pragma unroll
            for (int k = 0; k < 4; k++) acc[i][j][k] = 0.0f;

    const int nch = K / 64;
    load_stage(0, 0);

    for (int ch = 0; ch < nch; ch++) {
        asm volatile("cp.async.wait_group 0;" ::: "memory");
        __syncthreads();
        if (ch + 1 < nch) load_stage((ch + 1) & 1, (ch + 1) * 64);

        const uint32_t s0 = sb + (ch & 1) * FSTAGE;
#pragma unroll
        for (int ks = 0; ks < 4; ks++) {
            const uint32_t aoff = ((2 * ks + asel) ^ sx) << 4;
            const uint32_t boff = ((2 * ks + bsel) ^ sx) << 4;
            uint32_t b[2][8];
#pragma unroll
            for (int w = 0; w < 2; w++) {
                const uint32_t bw = s0 + (3 + w) * FT + (wn * 32 + brw) * 128 + boff;
                ldsm4(bw, b[w][0], b[w][1], b[w][2], b[w][3]);
                ldsm4(bw + 16 * 128, b[w][4], b[w][5], b[w][6], b[w][7]);
            }
            const int PA[3] = {0, 1, 2}, PW[3] = {0, 1, 0};
#pragma unroll
            for (int p = 0; p < 3; p++) {
                uint32_t a[4][4];
#pragma unroll
                for (int mf = 0; mf < 4; mf++)
                    ldsm4(s0 + PA[p] * FT + (wm * 64 + mf * 16 + arow) * 128 + aoff,
                          a[mf][0], a[mf][1], a[mf][2], a[mf][3]);
#pragma unroll
                for (int mf = 0; mf < 4; mf++)
#pragma unroll
                    for (int nf = 0; nf < 4; nf++)
                        mma16816(acc[mf][nf], a[mf], b[PW[p]][2 * nf], b[PW[p]][2 * nf + 1]);
            }
        }
        __syncthreads();
    }

    const int qr = lane >> 2, qc = (lane & 3) * 2;
#pragma unroll
    for (int mf = 0; mf < 4; mf++)
#pragma unroll
    for (int h2 = 0; h2 < 2; h2++) {
        const int row = brow + wm * 64 + mf * 16 + qr + 8 * h2;
#pragma unroll
        for (int nf = 0; nf < 4; nf++) {
            const int col = bcol + wn * 32 + nf * 8 + qc;
            const size_t ix = (size_t)row * N + col;
            float2 bb = *reinterpret_cast<const float2*>(bias + col);
            float m0  = acc[mf][nf][2 * h2 + 0] + bb.x;
            float m1v = acc[mf][nf][2 * h2 + 1] + bb.y;
            const bool sp0 = m0 > THRV, sp1 = m1v > THRV;
            *reinterpret_cast<float2*>(mem + ix) = make_float2(m0, m1v);
            uint32_t sv = (sp0 ? 0x1000u : 0u) | (sp1 ? 0x10000000u : 0u);
            *reinterpret_cast<uint32_t*>(spk + ix) = sv;
        }
    }
}

// ---------------------------------------------------------------------------
// Fused prep + readout
// ---------------------------------------------------------------------------
#define N_W1 (DIM_H1 * DIM_D)
#define N_W2 (DIM_H2 * DIM_H1)
#define N_X  (BATCH * DIM_D)

__global__ void __launch_bounds__(256)
prep_all(const float* __restrict__ W1, const float* __restrict__ W2,
         const float* __restrict__ x,
         __half* __restrict__ w1h, __half* __restrict__ w1l,
         __half* __restrict__ w1hu,
         __half* __restrict__ w2h, __half* __restrict__ w2l,
         __half* __restrict__ xh, __half* __restrict__ xl,
         __half* __restrict__ xhs)
{
    const int total = N_W1 + N_W2 + N_X;
    for (int i = blockIdx.x * 256 + threadIdx.x; i < total; i += gridDim.x * 256) {
        if (i < N_W1) {
            float v = W1[i] * 2048.0f;
            __half h = __float2half_rn(v);
            w1h[i] = h;
            w1l[i] = __float2half_rn(v - __half2float(h));
            w1hu[i] = __float2half_rn(__half2float(h) * (1.0f / 2048.0f));
        } else if (i < N_W1 + N_W2) {
            int j = i - N_W1;
            float v = W2[j] * 2048.0f;
            __half h = __float2half_rn(v);
            w2h[j] = h;
            w2l[j] = __float2half_rn(v - __half2float(h));
        } else {
            int j = i - N_W1 - N_W2;
            float v = x[j];
            __half h = __float2half_rn(v);
            xh[j] = h;
            xl[j] = __float2half_rn(v - __half2float(h));
            xhs[j] = __float2half_rn(__half2float(h) * (1.0f / 2048.0f));
        }
    }
}

__global__ void __launch_bounds__(256)
snn_readout(const float* __restrict__ spk_sum, const float* __restrict__ Wo,
            const float* __restrict__ bo, float* __restrict__ out)
{
    const int c  = threadIdx.x & 63;
    const int r4 = threadIdx.x >> 6;
    const size_t b = (size_t)blockIdx.x * 4 + r4;
    const float* s = spk_sum + b * DIM_H2;
    const float* w = Wo + (size_t)c * DIM_H2;
    float acc = 0.0f;
#pragma unroll 4
    for (int k = 0; k < DIM_H2; k += 4) {
        float4 sv = *reinterpret_cast<const float4*>(s + k);
        float4 wv = *reinterpret_cast<const float4*>(w + k);
        acc = fmaf(sv.x, wv.x, acc);
        acc = fmaf(sv.y, wv.y, acc);
        acc = fmaf(sv.z, wv.z, acc);
        acc = fmaf(sv.w, wv.w, acc);
    }
    out[b * DIM_C + c] = acc * (1.0f / (float)NUM_STEPS) + bo[c];
}

// ---------------------------------------------------------------------------
extern "C" void kernel_launch(void* const* d_in, const int* in_sizes, int n_in,
                              void* d_out, int out_size)
{
    const float* x  = (const float*)d_in[0];
    const float* W1 = (const float*)d_in[1];
    const float* b1 = (const float*)d_in[2];
    const float* W2 = (const float*)d_in[3];
    const float* b2 = (const float*)d_in[4];
    const float* Wo = (const float*)d_in[5];
    const float* bo = (const float*)d_in[6];
    float* out = (float*)d_out;

    auto sym = [](const void* s) { void* p; cudaGetSymbolAddress(&p, s); return p; };
    float*  m1   = (float*)sym(g_m1);
    float*  m2   = (float*)sym(g_m2);
    float*  spk  = (float*)sym(g_spk);
    __half* s1   = (__half*)sym(g_s1);
    __half* s2   = (__half*)sym(g_s2);
    __half* w1h  = (__half*)sym(g_w1h);
    __half* w1l  = (__half*)sym(g_w1l);
    __half* w1hu = (__half*)sym(g_w1hu);
    __half* w2h  = (__half*)sym(g_w2h);
    __half* w2l  = (__half*)sym(g_w2l);
    __half* xh   = (__half*)sym(g_xh);
    __half* xl   = (__half*)sym(g_xl);
    __half* xhs  = (__half*)sym(g_xhs);

    constexpr int SM_HYB = 3 * 3 * 16384 + 2 * 32768;  // 212992
    constexpr int SM_TZ  = 2 * 5 * 16384;              // 163840
    cudaFuncSetAttribute(snn_tz, cudaFuncAttributeMaxDynamicSharedMemorySize, SM_TZ);
    cudaFuncSetAttribute(snn_hyb<2048, 1536, true,  true >, cudaFuncAttributeMaxDynamicSharedMemorySize, SM_HYB);
    cudaFuncSetAttribute(snn_hyb<1024,  768, false, false>, cudaFuncAttributeMaxDynamicSharedMemorySize, SM_HYB);
    cudaFuncSetAttribute(snn_hyb<2048, 1536, false, true >, cudaFuncAttributeMaxDynamicSharedMemorySize, SM_HYB);

    prep_all<<<2048, 256>>>(W1, W2, x, w1h, w1l, w1hu, w2h, w2l, xh, xl, xhs);

    dim3 gtz(DIM_H1 / 128, BATCH / 128);   // (16, 32)
    dim3 g1 (DIM_H1 / 128, BATCH / 128);   // (16, 32)
    dim3 g2 (DIM_H2 / 128, BATCH / 128);   // (8, 32)

    // t = 0 (mem starts at zero)
    snn_tz<<<gtz, 256, SM_TZ>>>(xh, xhs, xl, w1hu, w1l, b1, m1, s1, DIM_H1, DIM_D);
    snn_hyb<2048, 1536, true, true><<<g2, 512, SM_HYB>>>(
        s1, w2h, w2l, W2, b2, m2, s2, spk, DIM_H2);

    for (int t = 1; t < NUM_STEPS; t++) {
        snn_hyb<1024, 768, false, false><<<g1, 512, SM_HYB>>>(
            s2, w1h, w1l, W1, b1, m1, s1, nullptr, DIM_H1);
        snn_hyb<2048, 1536, false, true><<<g2, 512, SM_HYB>>>(
            s1, w2h, w2l, W2, b2, m2, s2, spk, DIM_H2);
    }

    snn_readout<<<BATCH / 4, 256>>>(spk, Wo, bo, out);
}

// round 8
// speedup vs baseline: 1.8858x; 1.8858x over previous
#include <cuda_runtime.h>
#include <cuda_fp16.h>
#include <cstdint>

// ===========================================================================
// SNN (20 steps, 2 fused Linear+LIF layers + feedback) on mma.sync (HMMA).
// Spikes stored as exactly 2^-11, weights split into 2 fp16 limbs scaled by
// 2^11 -> products exact, residual ~|w|*2^-24 (fp32-identical trajectory).
// Round 8: round-6 baseline + spike-sum kept in fp16 (exact integers <= 20)
// to halve the SUM-epilogue global traffic.
// ===========================================================================

#define BATCH   4096
#define DIM_D   1024
#define DIM_H1  2048
#define DIM_H2  1024
#define DIM_C   64
#define NUM_STEPS 20
#define BETA 0.9f
#define THRV 1.0f

// ---------------------------------------------------------------------------
// Device-global state / scratch
// ---------------------------------------------------------------------------
__device__ float  g_m1 [(size_t)BATCH * DIM_H1];
__device__ float  g_m2 [(size_t)BATCH * DIM_H2];
__device__ __half g_spk[(size_t)BATCH * DIM_H2];    // spike counts (fp16 ints)
__device__ __half g_s1 [(size_t)BATCH * DIM_H1];
__device__ __half g_s2 [(size_t)BATCH * DIM_H2];
__device__ __half g_w1h [(size_t)DIM_H1 * DIM_D];   // W1 * 2^11, hi limb
__device__ __half g_w1l [(size_t)DIM_H1 * DIM_D];   // W1 * 2^11, lo limb
__device__ __half g_w1hu[(size_t)DIM_H1 * DIM_D];   // W1 hi limb, unscaled (t=0)
__device__ __half g_w2h [(size_t)DIM_H2 * DIM_H1];
__device__ __half g_w2l [(size_t)DIM_H2 * DIM_H1];
__device__ __half g_xh  [(size_t)BATCH * DIM_D];    // fp16(x)
__device__ __half g_xl  [(size_t)BATCH * DIM_D];    // fp16(x - xh)
__device__ __half g_xhs [(size_t)BATCH * DIM_D];    // fp16(xh * 2^-11)

// ---------------------------------------------------------------------------
// PTX helpers
// ---------------------------------------------------------------------------
__device__ __forceinline__ uint32_t smem_u32(const void* p) {
    uint32_t a;
    asm("{ .reg .u64 t; cvta.to.shared.u64 t, %1; cvt.u32.u64 %0, t; }"
        : "=r"(a) : "l"(p));
    return a;
}
__device__ __forceinline__ void cp16(uint32_t dst, const void* src) {
    asm volatile("cp.async.cg.shared.global [%0], [%1], 16;"
                 :: "r"(dst), "l"(__cvta_generic_to_global(src)) : "memory");
}
__device__ __forceinline__ void ldsm4(uint32_t addr, uint32_t& r0, uint32_t& r1,
                                      uint32_t& r2, uint32_t& r3) {
    asm volatile("ldmatrix.sync.aligned.m8n8.x4.shared.b16 {%0,%1,%2,%3}, [%4];"
                 : "=r"(r0), "=r"(r1), "=r"(r2), "=r"(r3) : "r"(addr));
}
__device__ __forceinline__ void mma16816(float* c, const uint32_t a[4],
                                         uint32_t b0, uint32_t b1) {
    asm volatile(
        "mma.sync.aligned.m16n8k16.row.col.f32.f16.f16.f32 "
        "{%0,%1,%2,%3}, {%4,%5,%6,%7}, {%8,%9}, {%0,%1,%2,%3};"
        : "+f"(c[0]), "+f"(c[1]), "+f"(c[2]), "+f"(c[3])
        : "r"(a[0]), "r"(a[1]), "r"(a[2]), "r"(a[3]), "r"(b0), "r"(b1));
}

// ---------------------------------------------------------------------------
// Fused GEMM + LIF.  D[row,col] = sum_k A[row,k] * W[col,k]  (+ limb products)
// TZ=false: A=spikes(2^-11), products (A,W0)+(A,W1), W limbs scaled 2^11.
// TZ=true : A limbs {xh, xh*2^-11, xl}, products (0,W0),(1,W1),(2,W0),
//           W0 = unscaled hi limb, W1 = lo limb * 2^11.
// 128x128 CTA tile, 8 warps (2m x 4n), warp tile 64x32, BK=64, 2 stages.
// ---------------------------------------------------------------------------
template <bool TZ, bool FIRST, bool SUM>
__global__ void __launch_bounds__(256, 2)
snn_hmma(const __half* __restrict__ A0, const __half* __restrict__ A1,
         const __half* __restrict__ A2,
         const __half* __restrict__ W0, const __half* __restrict__ W1,
         const float* __restrict__ bias, float* __restrict__ mem,
         __half* __restrict__ spk, __half* __restrict__ spk_sum,
         int N, int K)
{
    constexpr int NA = TZ ? 3 : 1;
    constexpr int TILE = 16384;                 // 128 rows x 128 bytes
    constexpr int STAGE = (NA + 2) * TILE;
    extern __shared__ char smem[];
    const uint32_t sb = smem_u32(smem);

    const int tid = threadIdx.x, lane = tid & 31, wid = tid >> 5;
    const int wm = wid >> 2, wn = wid & 3;
    const int brow = blockIdx.y * 128, bcol = blockIdx.x * 128;

    const __half* Ap[3];
    Ap[0] = A0 + (size_t)brow * K;
    Ap[1] = TZ ? A1 + (size_t)brow * K : Ap[0];
    Ap[2] = TZ ? A2 + (size_t)brow * K : Ap[0];
    const __half* Wp[2] = { W0 + (size_t)bcol * K, W1 + (size_t)bcol * K };

    auto load_stage = [&](int st, int k0) {
        const uint32_t s0 = sb + st * STAGE;
#pragma unroll
        for (int l = 0; l < NA; l++) {
            const __half* g = Ap[l];
            const uint32_t d = s0 + l * TILE;
            for (int q = tid; q < 1024; q += 256) {
                int r = q >> 3, c = q & 7;
                cp16(d + r * 128 + ((c ^ (r & 7)) << 4),
                     g + (size_t)r * K + k0 + c * 8);
            }
        }
#pragma unroll
        for (int l = 0; l < 2; l++) {
            const __half* g = Wp[l];
            const uint32_t d = s0 + (NA + l) * TILE;
            for (int q = tid; q < 1024; q += 256) {
                int r = q >> 3, c = q & 7;
                cp16(d + r * 128 + ((c ^ (r & 7)) << 4),
                     g + (size_t)r * K + k0 + c * 8);
            }
        }
        asm volatile("cp.async.commit_group;" ::: "memory");
    };

    // ldmatrix lane geometry
    const int arow = (lane & 7) + 8 * ((lane >> 3) & 1);   // A: m within 16
    const int asel = lane >> 4;                            // A: k-chunk select
    const int brw  = (lane & 7) + 8 * (lane >> 4);         // B: n within 16
    const int bsel = (lane >> 3) & 1;                      // B: k-chunk select
    const int sx   = lane & 7;                             // swizzle key

    float acc[4][4][4];
#pragma unroll
    for (int i = 0; i < 4; i++)
#pragma unroll
        for (int j = 0; j < 4; j++)
#pragma unroll
            for (int k = 0; k < 4; k++) acc[i][j][k] = 0.0f;

    const int nch = K / 64;
    load_stage(0, 0);

    for (int ch = 0; ch < nch; ch++) {
        if (ch + 1 < nch) {
            load_stage((ch + 1) & 1, (ch + 1) * 64);
            asm volatile("cp.async.wait_group 1;" ::: "memory");
        } else {
            asm volatile("cp.async.wait_group 0;" ::: "memory");
        }
        __syncthreads();

        const uint32_t s0 = sb + (ch & 1) * STAGE;
        uint32_t bb[2][2];
#pragma unroll
        for (int w = 0; w < 2; w++)
#pragma unroll
            for (int h = 0; h < 2; h++)
                bb[w][h] = s0 + (NA + w) * TILE + (wn * 32 + h * 16 + brw) * 128;

#pragma unroll
        for (int ks = 0; ks < 4; ks++) {
            uint32_t b[2][8];
#pragma unroll
            for (int w = 0; w < 2; w++) {
                const uint32_t off = ((2 * ks + bsel) ^ sx) << 4;
                ldsm4(bb[w][0] + off, b[w][0], b[w][1], b[w][2], b[w][3]);
                ldsm4(bb[w][1] + off, b[w][4], b[w][5], b[w][6], b[w][7]);
            }
            const uint32_t aoff = ((2 * ks + asel) ^ sx) << 4;
            if (!TZ) {
                uint32_t a[4][4];
#pragma unroll
                for (int mf = 0; mf < 4; mf++)
                    ldsm4(s0 + (wm * 64 + mf * 16 + arow) * 128 + aoff,
                          a[mf][0], a[mf][1], a[mf][2], a[mf][3]);
#pragma unroll
                for (int w = 0; w < 2; w++)
#pragma unroll
                    for (int mf = 0; mf < 4; mf++)
#pragma unroll
                        for (int nf = 0; nf < 4; nf++)
                            mma16816(acc[mf][nf], a[mf], b[w][2 * nf], b[w][2 * nf + 1]);
            } else {
                const int PA[3] = {0, 1, 2}, PW[3] = {0, 1, 0};
#pragma unroll
                for (int p = 0; p < 3; p++) {
                    uint32_t a[4][4];
#pragma unroll
                    for (int mf = 0; mf < 4; mf++)
                        ldsm4(s0 + PA[p] * TILE + (wm * 64 + mf * 16 + arow) * 128 + aoff,
                              a[mf][0], a[mf][1], a[mf][2], a[mf][3]);
#pragma unroll
                    for (int mf = 0; mf < 4; mf++)
#pragma unroll
                        for (int nf = 0; nf < 4; nf++)
                            mma16816(acc[mf][nf], a[mf], b[PW[p]][2 * nf], b[PW[p]][2 * nf + 1]);
                }
            }
        }
        __syncthreads();
    }

    // ---- Fused LIF epilogue on register accumulators ----
    const int qr = lane >> 2, qc = (lane & 3) * 2;
#pragma unroll
    for (int mf = 0; mf < 4; mf++)
#pragma unroll
    for (int h = 0; h < 2; h++) {
        const int row = brow + wm * 64 + mf * 16 + qr + 8 * h;
#pragma unroll
        for (int nf = 0; nf < 4; nf++) {
            const int col = bcol + wn * 32 + nf * 8 + qc;
            const size_t ix = (size_t)row * N + col;
            float2 bb = *reinterpret_cast<const float2*>(bias + col);
            float v0 = acc[mf][nf][2 * h + 0] + bb.x;
            float v1 = acc[mf][nf][2 * h + 1] + bb.y;
            float m0, m1v;
            if (FIRST) {
                m0 = v0; m1v = v1;
            } else {
                float2 mo = *reinterpret_cast<const float2*>(mem + ix);
                m0  = BETA * mo.x + v0 - ((mo.x > THRV) ? THRV : 0.0f);
                m1v = BETA * mo.y + v1 - ((mo.y > THRV) ? THRV : 0.0f);
            }
            const bool sp0 = m0 > THRV, sp1 = m1v > THRV;
            *reinterpret_cast<float2*>(mem + ix) = make_float2(m0, m1v);
            // spike value = 2^-11 exactly (fp16 bits 0x1000)
            uint32_t sv = (sp0 ? 0x1000u : 0u) | (sp1 ? 0x10000000u : 0u);
            *reinterpret_cast<uint32_t*>(spk + ix) = sv;
            if (SUM) {
                // spike counts as fp16 integers (exact up to 2048)
                __half2 add = __floats2half2_rn(sp0 ? 1.0f : 0.0f,
                                                sp1 ? 1.0f : 0.0f);
                __half2* ss = reinterpret_cast<__half2*>(spk_sum + ix);
                if (FIRST) *ss = add;
                else       *ss = __hadd2(*ss, add);
            }
        }
    }
}

// ---------------------------------------------------------------------------
// Fused prep: W1 split (3 outs), W2 split (2 outs), x split (3 outs).
// ---------------------------------------------------------------------------
#define N_W1 (DIM_H1 * DIM_D)
#define N_W2 (DIM_H2 * DIM_H1)
#define N_X  (BATCH * DIM_D)

__global__ void __launch_bounds__(256)
prep_all(const float* __restrict__ W1, const float* __restrict__ W2,
         const float* __restrict__ x,
         __half* __restrict__ w1h, __half* __restrict__ w1l,
         __half* __restrict__ w1hu,
         __half* __restrict__ w2h, __half* __restrict__ w2l,
         __half* __restrict__ xh, __half* __restrict__ xl,
         __half* __restrict__ xhs)
{
    const int total = N_W1 + N_W2 + N_X;
    for (int i = blockIdx.x * 256 + threadIdx.x; i < total; i += gridDim.x * 256) {
        if (i < N_W1) {
            float v = W1[i] * 2048.0f;
            __half h = __float2half_rn(v);
            w1h[i] = h;
            w1l[i] = __float2half_rn(v - __half2float(h));
            w1hu[i] = __float2half_rn(__half2float(h) * (1.0f / 2048.0f));
        } else if (i < N_W1 + N_W2) {
            int j = i - N_W1;
            float v = W2[j] * 2048.0f;
            __half h = __float2half_rn(v);
            w2h[j] = h;
            w2l[j] = __float2half_rn(v - __half2float(h));
        } else {
            int j = i - N_W1 - N_W2;
            float v = x[j];
            __half h = __float2half_rn(v);
            xh[j] = h;
            xl[j] = __float2half_rn(v - __half2float(h));
            xhs[j] = __float2half_rn(__half2float(h) * (1.0f / 2048.0f));
        }
    }
}

// ---------------------------------------------------------------------------
// Readout: out[b,c] = (spk_sum[b,:]/NUM_STEPS) . Wo[c,:] + bo[c]
// spk_sum is fp16 integer counts (exact); accumulate in fp32 as before.
// ---------------------------------------------------------------------------
__global__ void __launch_bounds__(256)
snn_readout(const __half* __restrict__ spk_sum, const float* __restrict__ Wo,
            const float* __restrict__ bo, float* __restrict__ out)
{
    const int c  = threadIdx.x & 63;
    const int r4 = threadIdx.x >> 6;
    const size_t b = (size_t)blockIdx.x * 4 + r4;
    const __half* s = spk_sum + b * DIM_H2;
    const float* w = Wo + (size_t)c * DIM_H2;
    float acc = 0.0f;
#pragma unroll 4
    for (int k = 0; k < DIM_H2; k += 4) {
        __half2 s01 = *reinterpret_cast<const __half2*>(s + k);
        __half2 s23 = *reinterpret_cast<const __half2*>(s + k + 2);
        float2 f01 = __half22float2(s01);
        float2 f23 = __half22float2(s23);
        float4 wv = *reinterpret_cast<const float4*>(w + k);
        acc = fmaf(f01.x, wv.x, acc);
        acc = fmaf(f01.y, wv.y, acc);
        acc = fmaf(f23.x, wv.z, acc);
        acc = fmaf(f23.y, wv.w, acc);
    }
    out[b * DIM_C + c] = acc * (1.0f / (float)NUM_STEPS) + bo[c];
}

// ---------------------------------------------------------------------------
extern "C" void kernel_launch(void* const* d_in, const int* in_sizes, int n_in,
                              void* d_out, int out_size)
{
    const float* x  = (const float*)d_in[0];
    const float* W1 = (const float*)d_in[1];
    const float* b1 = (const float*)d_in[2];
    const float* W2 = (const float*)d_in[3];
    const float* b2 = (const float*)d_in[4];
    const float* Wo = (const float*)d_in[5];
    const float* bo = (const float*)d_in[6];
    float* out = (float*)d_out;

    auto sym = [](const void* s) { void* p; cudaGetSymbolAddress(&p, s); return p; };
    float*  m1   = (float*)sym(g_m1);
    float*  m2   = (float*)sym(g_m2);
    __half* spk  = (__half*)sym(g_spk);
    __half* s1   = (__half*)sym(g_s1);
    __half* s2   = (__half*)sym(g_s2);
    __half* w1h  = (__half*)sym(g_w1h);
    __half* w1l  = (__half*)sym(g_w1l);
    __half* w1hu = (__half*)sym(g_w1hu);
    __half* w2h  = (__half*)sym(g_w2h);
    __half* w2l  = (__half*)sym(g_w2l);
    __half* xh   = (__half*)sym(g_xh);
    __half* xl   = (__half*)sym(g_xl);
    __half* xhs  = (__half*)sym(g_xhs);

    constexpr int SM_STD = 2 * 3 * 16384;   //  98304 B -> 2 CTA/SM
    constexpr int SM_TZ  = 2 * 5 * 16384;   // 163840 B -> 1 CTA/SM (runs once)
    cudaFuncSetAttribute(snn_hmma<true,  true,  false>, cudaFuncAttributeMaxDynamicSharedMemorySize, SM_TZ);
    cudaFuncSetAttribute(snn_hmma<false, true,  true >, cudaFuncAttributeMaxDynamicSharedMemorySize, SM_STD);
    cudaFuncSetAttribute(snn_hmma<false, false, false>, cudaFuncAttributeMaxDynamicSharedMemorySize, SM_STD);
    cudaFuncSetAttribute(snn_hmma<false, false, true >, cudaFuncAttributeMaxDynamicSharedMemorySize, SM_STD);

    prep_all<<<2048, 256>>>(W1, W2, x, w1h, w1l, w1hu, w2h, w2l, xh, xl, xhs);

    dim3 blk(256);
    dim3 g1(DIM_H1 / 128, BATCH / 128);   // (16, 32)
    dim3 g2(DIM_H2 / 128, BATCH / 128);   // (8, 32)

    // t = 0 (mem starts at zero)
    snn_hmma<true, true, false><<<g1, blk, SM_TZ>>>(
        xh, xhs, xl, w1hu, w1l, b1, m1, s1, nullptr, DIM_H1, DIM_D);
    snn_hmma<false, true, true><<<g2, blk, SM_STD>>>(
        s1, nullptr, nullptr, w2h, w2l, b2, m2, s2, spk, DIM_H2, DIM_H1);

    for (int t = 1; t < NUM_STEPS; t++) {
        snn_hmma<false, false, false><<<g1, blk, SM_STD>>>(
            s2, nullptr, nullptr, w1h, w1l, b1, m1, s1, nullptr, DIM_H1, DIM_D);
        snn_hmma<false, false, true><<<g2, blk, SM_STD>>>(
            s1, nullptr, nullptr, w2h, w2l, b2, m2, s2, spk, DIM_H2, DIM_H1);
    }

    snn_readout<<<BATCH / 4, blk>>>(spk, Wo, bo, out);
}

// round 9
// speedup vs baseline: 2.1802x; 1.1561x over previous
#include <cuda_runtime.h>
#include <cuda_fp16.h>
#include <cstdint>

// ===========================================================================
// SNN (20 steps, 2 fused Linear+LIF + feedback) on mma.sync (HMMA).
// Spikes = exactly 2^-11 in fp16; weights split into 2 fp16 limbs scaled by
// 2^11 -> products exact, residual ~|w|*2^-24 (fp32-identical trajectory).
// Round 9: ONE persistent kernel for all 39 steady GEMM+LIF stages.
// Tile queue (global atomic ticket) + row-block ready counters implement the
// cross-layer/cross-step dataflow, eliminating launch-boundary pipe drains
// and wave-quantization tails.
// ===========================================================================

#define BATCH   4096
#define DIM_D   1024
#define DIM_H1  2048
#define DIM_H2  1024
#define DIM_C   64
#define NUM_STEPS 20
#define BETA 0.9f
#define THRV 1.0f

#define RB_COUNT 32                 // 4096/128 row blocks
#define L1_CB 16                    // 2048/128
#define L2_CB 8                     // 1024/128
#define TILES_PER_STEP (RB_COUNT * (L1_CB + L2_CB))        // 768
#define TOT_TILES (RB_COUNT * L2_CB + (NUM_STEPS - 1) * TILES_PER_STEP)  // 14848

// ---------------------------------------------------------------------------
// Device-global state / scratch
// ---------------------------------------------------------------------------
__device__ float  g_m1 [(size_t)BATCH * DIM_H1];
__device__ float  g_m2 [(size_t)BATCH * DIM_H2];
__device__ __half g_spk[(size_t)BATCH * DIM_H2];    // spike counts (fp16 ints)
__device__ __half g_s1 [(size_t)BATCH * DIM_H1];
__device__ __half g_s2 [(size_t)BATCH * DIM_H2];
__device__ __half g_w1h [(size_t)DIM_H1 * DIM_D];
__device__ __half g_w1l [(size_t)DIM_H1 * DIM_D];
__device__ __half g_w1hu[(size_t)DIM_H1 * DIM_D];
__device__ __half g_w2h [(size_t)DIM_H2 * DIM_H1];
__device__ __half g_w2l [(size_t)DIM_H2 * DIM_H1];
__device__ __half g_xh  [(size_t)BATCH * DIM_D];
__device__ __half g_xl  [(size_t)BATCH * DIM_D];
__device__ __half g_xhs [(size_t)BATCH * DIM_D];
// Scheduler state (zeroed by prep_all each launch)
__device__ unsigned g_ticket;
__device__ unsigned g_cnt1[NUM_STEPS][RB_COUNT];   // L1 tiles done per (t, rb)
__device__ unsigned g_cnt2[NUM_STEPS][RB_COUNT];   // L2 tiles done per (t, rb)

// ---------------------------------------------------------------------------
// PTX helpers
// ---------------------------------------------------------------------------
__device__ __forceinline__ uint32_t smem_u32(const void* p) {
    uint32_t a;
    asm("{ .reg .u64 t; cvta.to.shared.u64 t, %1; cvt.u32.u64 %0, t; }"
        : "=r"(a) : "l"(p));
    return a;
}
__device__ __forceinline__ void cp16(uint32_t dst, const void* src) {
    asm volatile("cp.async.cg.shared.global [%0], [%1], 16;"
                 :: "r"(dst), "l"(__cvta_generic_to_global(src)) : "memory");
}
__device__ __forceinline__ void ldsm4(uint32_t addr, uint32_t& r0, uint32_t& r1,
                                      uint32_t& r2, uint32_t& r3) {
    asm volatile("ldmatrix.sync.aligned.m8n8.x4.shared.b16 {%0,%1,%2,%3}, [%4];"
                 : "=r"(r0), "=r"(r1), "=r"(r2), "=r"(r3) : "r"(addr));
}
__device__ __forceinline__ void mma16816(float* c, const uint32_t a[4],
                                         uint32_t b0, uint32_t b1) {
    asm volatile(
        "mma.sync.aligned.m16n8k16.row.col.f32.f16.f16.f32 "
        "{%0,%1,%2,%3}, {%4,%5,%6,%7}, {%8,%9}, {%0,%1,%2,%3};"
        : "+f"(c[0]), "+f"(c[1]), "+f"(c[2]), "+f"(c[3])
        : "r"(a[0]), "r"(a[1]), "r"(a[2]), "r"(a[3]), "r"(b0), "r"(b1));
}

// ===========================================================================
// Persistent steady-state kernel. One CTA = 256 threads; pulls tiles from the
// global ticket; each tile = 128x128 GEMM(+LIF) exactly as the round-3 config.
// ===========================================================================
__global__ void __launch_bounds__(256, 2)
snn_persist(const __half* __restrict__ w1h, const __half* __restrict__ w1l,
            const __half* __restrict__ w2h, const __half* __restrict__ w2l,
            const float* __restrict__ b1, const float* __restrict__ b2,
            float* __restrict__ m1, float* __restrict__ m2,
            __half* __restrict__ s1, __half* __restrict__ s2,
            __half* __restrict__ spk_sum)
{
    constexpr int TILE = 16384;                 // 128 rows x 128 bytes
    constexpr int STAGE = 3 * TILE;             // A + Wh + Wl
    extern __shared__ char smem[];
    unsigned* shdr = reinterpret_cast<unsigned*>(smem);
    const uint32_t sb = smem_u32(smem) + 1024;  // stages after 1KB header

    const int tid = threadIdx.x, lane = tid & 31, wid = tid >> 5;
    const int wm = wid >> 2, wn = wid & 3;

    // ldmatrix lane geometry (loop-invariant)
    const int arow = (lane & 7) + 8 * ((lane >> 3) & 1);
    const int asel = lane >> 4;
    const int brw  = (lane & 7) + 8 * (lane >> 4);
    const int bsel = (lane >> 3) & 1;
    const int sx   = lane & 7;
    const int qr   = lane >> 2, qc = (lane & 3) * 2;

    for (;;) {
        // ---- pull next tile ----
        __syncthreads();
        if (tid == 0) shdr[0] = atomicAdd(&g_ticket, 1u);
        __syncthreads();
        const unsigned ti = shdr[0];
        if (ti >= TOT_TILES) break;

        // ---- decode (t, layer, rb, cb); rb-major within each segment ----
        int t, layer, rb, cb;
        if (ti < RB_COUNT * L2_CB) {
            t = 0; layer = 2; rb = ti >> 3; cb = ti & 7;
        } else {
            const unsigned j = ti - RB_COUNT * L2_CB;
            t = 1 + (int)(j / TILES_PER_STEP);
            const unsigned r = j % TILES_PER_STEP;
            if (r < RB_COUNT * L1_CB) { layer = 1; rb = r >> 4; cb = r & 15; }
            else { const unsigned q = r - RB_COUNT * L1_CB; layer = 2; rb = q >> 3; cb = q & 7; }
        }

        // ---- dependency wait (row-block granularity) ----
        if (tid == 0) {
            volatile unsigned* dep = nullptr;
            unsigned tgt = 0;
            if (layer == 1)      { dep = &g_cnt2[t - 1][rb]; tgt = L2_CB; }
            else if (t > 0)      { dep = &g_cnt1[t][rb];     tgt = L1_CB; }
            if (dep) while (*dep < tgt) __nanosleep(64);
        }
        __syncthreads();
        __threadfence();   // order subsequent loads after observed release

        // ---- per-tile parameters ----
        const int K = (layer == 1) ? DIM_H2 : DIM_H1;       // 1024 / 2048
        const int N = (layer == 1) ? DIM_H1 : DIM_H2;       // 2048 / 1024
        const __half* A  = (layer == 1) ? s2  : s1;
        const __half* W0 = (layer == 1) ? w1h : w2h;
        const __half* W1 = (layer == 1) ? w1l : w2l;
        const float* bias = (layer == 1) ? b1 : b2;
        float* mem = (layer == 1) ? m1 : m2;
        __half* spko = (layer == 1) ? s1 : s2;
        const bool SUMf = (layer == 2);
        const bool FIRSTf = (layer == 2) && (t == 0);
        const int brow = rb * 128, bcol = cb * 128;

        const __half* Ab = A + (size_t)brow * K;
        const __half* Wp0 = W0 + (size_t)bcol * K;
        const __half* Wp1 = W1 + (size_t)bcol * K;

        auto load_stage = [&](int st, int k0) {
            const uint32_t s0 = sb + st * STAGE;
            for (int q = tid; q < 1024; q += 256) {
                int r = q >> 3, c = q & 7;
                cp16(s0 + r * 128 + ((c ^ (r & 7)) << 4),
                     Ab + (size_t)r * K + k0 + c * 8);
            }
            for (int q = tid; q < 1024; q += 256) {
                int r = q >> 3, c = q & 7;
                cp16(s0 + TILE + r * 128 + ((c ^ (r & 7)) << 4),
                     Wp0 + (size_t)r * K + k0 + c * 8);
            }
            for (int q = tid; q < 1024; q += 256) {
                int r = q >> 3, c = q & 7;
                cp16(s0 + 2 * TILE + r * 128 + ((c ^ (r & 7)) << 4),
                     Wp1 + (size_t)r * K + k0 + c * 8);
            }
            asm volatile("cp.async.commit_group;" ::: "memory");
        };

        float acc[4][4][4];
#pragma unroll
        for (int i = 0; i < 4; i++)
#pragma unroll
            for (int j = 0; j < 4; j++)
#pragma unroll
                for (int k = 0; k < 4; k++) acc[i][j][k] = 0.0f;

        const int nch = K / 64;
        load_stage(0, 0);

        for (int ch = 0; ch < nch; ch++) {
            if (ch + 1 < nch) {
                load_stage((ch + 1) & 1, (ch + 1) * 64);
                asm volatile("cp.async.wait_group 1;" ::: "memory");
            } else {
                asm volatile("cp.async.wait_group 0;" ::: "memory");
            }
            __syncthreads();

            const uint32_t s0 = sb + (ch & 1) * STAGE;
            uint32_t bb[2][2];
#pragma unroll
            for (int w = 0; w < 2; w++)
#pragma unroll
                for (int h = 0; h < 2; h++)
                    bb[w][h] = s0 + (1 + w) * TILE + (wn * 32 + h * 16 + brw) * 128;

#pragma unroll
            for (int ks = 0; ks < 4; ks++) {
                uint32_t b[2][8];
#pragma unroll
                for (int w = 0; w < 2; w++) {
                    const uint32_t off = ((2 * ks + bsel) ^ sx) << 4;
                    ldsm4(bb[w][0] + off, b[w][0], b[w][1], b[w][2], b[w][3]);
                    ldsm4(bb[w][1] + off, b[w][4], b[w][5], b[w][6], b[w][7]);
                }
                const uint32_t aoff = ((2 * ks + asel) ^ sx) << 4;
                uint32_t a[4][4];
#pragma unroll
                for (int mf = 0; mf < 4; mf++)
                    ldsm4(s0 + (wm * 64 + mf * 16 + arow) * 128 + aoff,
                          a[mf][0], a[mf][1], a[mf][2], a[mf][3]);
#pragma unroll
                for (int w = 0; w < 2; w++)
#pragma unroll
                    for (int mf = 0; mf < 4; mf++)
#pragma unroll
                        for (int nf = 0; nf < 4; nf++)
                            mma16816(acc[mf][nf], a[mf], b[w][2 * nf], b[w][2 * nf + 1]);
            }
            __syncthreads();
        }

        // ---- fused LIF epilogue ----
#pragma unroll
        for (int mf = 0; mf < 4; mf++)
#pragma unroll
        for (int h = 0; h < 2; h++) {
            const int row = brow + wm * 64 + mf * 16 + qr + 8 * h;
#pragma unroll
            for (int nf = 0; nf < 4; nf++) {
                const int col = bcol + wn * 32 + nf * 8 + qc;
                const size_t ix = (size_t)row * N + col;
                float2 bb = *reinterpret_cast<const float2*>(bias + col);
                float v0 = acc[mf][nf][2 * h + 0] + bb.x;
                float v1 = acc[mf][nf][2 * h + 1] + bb.y;
                float m0, m1v;
                if (FIRSTf) {
                    m0 = v0; m1v = v1;
                } else {
                    float2 mo = *reinterpret_cast<const float2*>(mem + ix);
                    m0  = BETA * mo.x + v0 - ((mo.x > THRV) ? THRV : 0.0f);
                    m1v = BETA * mo.y + v1 - ((mo.y > THRV) ? THRV : 0.0f);
                }
                const bool sp0 = m0 > THRV, sp1 = m1v > THRV;
                *reinterpret_cast<float2*>(mem + ix) = make_float2(m0, m1v);
                uint32_t sv = (sp0 ? 0x1000u : 0u) | (sp1 ? 0x10000000u : 0u);
                *reinterpret_cast<uint32_t*>(spko + ix) = sv;
                if (SUMf) {
                    __half2 add = __floats2half2_rn(sp0 ? 1.0f : 0.0f,
                                                    sp1 ? 1.0f : 0.0f);
                    __half2* ss = reinterpret_cast<__half2*>(spk_sum + ix);
                    if (FIRSTf) *ss = add;
                    else        *ss = __hadd2(*ss, add);
                }
            }
        }

        // ---- release ----
        __threadfence();
        __syncthreads();
        if (tid == 0) {
            unsigned* rel = (layer == 1) ? &g_cnt1[t][rb] : &g_cnt2[t][rb];
            atomicAdd(rel, 1u);
        }
    }
}

// ===========================================================================
// t=0 layer-1 kernel (real-valued x, 3 fp16 limb products). Runs once.
// ===========================================================================
__global__ void __launch_bounds__(256, 2)
snn_tz(const __half* __restrict__ A0, const __half* __restrict__ A1,
       const __half* __restrict__ A2,
       const __half* __restrict__ W0, const __half* __restrict__ W1,
       const float* __restrict__ bias, float* __restrict__ mem,
       __half* __restrict__ spk, int N, int K)
{
    constexpr int FT = 16384;
    constexpr int FSTAGE = 5 * FT;
    extern __shared__ char smem[];
    const uint32_t sb = smem_u32(smem);

    const int tid = threadIdx.x, lane = tid & 31, wid = tid >> 5;
    const int wm = wid >> 2, wn = wid & 3;
    const int brow = blockIdx.y * 128, bcol = blockIdx.x * 128;

    const __half* Ap[3] = { A0 + (size_t)brow * K, A1 + (size_t)brow * K,
                            A2 + (size_t)brow * K };
    const __half* Wp[2] = { W0 + (size_t)bcol * K, W1 + (size_t)bcol * K };

    auto load_stage = [&](int st, int k0) {
        const uint32_t s0 = sb + st * FSTAGE;
#pragma unroll
        for (int l = 0; l < 3; l++) {
            const uint32_t d = s0 + l * FT;
            for (int q = tid; q < 1024; q += 256) {
                int r = q >> 3, c = q & 7;
                cp16(d + r * 128 + ((c ^ (r & 7)) << 4),
                     Ap[l] + (size_t)r * K + k0 + c * 8);
            }
        }
#pragma unroll
        for (int l = 0; l < 2; l++) {
            const uint32_t d = s0 + (3 + l) * FT;
            for (int q = tid; q < 1024; q += 256) {
                int r = q >> 3, c = q & 7;
                cp16(d + r * 128 + ((c ^ (r & 7)) << 4),
                     Wp[l] + (size_t)r * K + k0 + c * 8);
            }
        }
        asm volatile("cp.async.commit_group;" ::: "memory");
    };

    const int arow = (lane & 7) + 8 * ((lane >> 3) & 1);
    const int asel = lane >> 4;
    const int brw  = (lane & 7) + 8 * (lane >> 4);
    const int bsel = (lane >> 3) & 1;
    const int sx   = lane & 7;

    float acc[4][4][4];
#pragma unroll
    for (int i = 0; i < 4; i++)
#pragma unroll
        for (int j = 0; j < 4; j++)
#pragma unroll
            for (int k = 0; k < 4; k++) acc[i][j][k] = 0.0f;

    const int nch = K / 64;
    load_stage(0, 0);

    for (int ch = 0; ch < nch; ch++) {
        asm volatile("cp.async.wait_group 0;" ::: "memory");
        __syncthreads();
        if (ch + 1 < nch) load_stage((ch + 1) & 1, (ch + 1) * 64);

        const uint32_t s0 = sb + (ch & 1) * FSTAGE;
#pragma unroll
        for (int ks = 0; ks < 4; ks++) {
            const uint32_t aoff = ((2 * ks + asel) ^ sx) << 4;
            const uint32_t boff = ((2 * ks + bsel) ^ sx) << 4;
            uint32_t b[2][8];
#pragma unroll
            for (int w = 0; w < 2; w++) {
                const uint32_t bw = s0 + (3 + w) * FT + (wn * 32 + brw) * 128 + boff;
                ldsm4(bw, b[w][0], b[w][1], b[w][2], b[w][3]);
                ldsm4(bw + 16 * 128, b[w][4], b[w][5], b[w][6], b[w][7]);
            }
            const int PA[3] = {0, 1, 2}, PW[3] = {0, 1, 0};
#pragma unroll
            for (int p = 0; p < 3; p++) {
                uint32_t a[4][4];
#pragma unroll
                for (int mf = 0; mf < 4; mf++)
                    ldsm4(s0 + PA[p] * FT + (wm * 64 + mf * 16 + arow) * 128 + aoff,
                          a[mf][0], a[mf][1], a[mf][2], a[mf][3]);
#pragma unroll
                for (int mf = 0; mf < 4; mf++)
#pragma unroll
                    for (int nf = 0; nf < 4; nf++)
                        mma16816(acc[mf][nf], a[mf], b[PW[p]][2 * nf], b[PW[p]][2 * nf + 1]);
            }
        }
        __syncthreads();
    }

    const int qr = lane >> 2, qc = (lane & 3) * 2;
#pragma unroll
    for (int mf = 0; mf < 4; mf++)
#pragma unroll
    for (int h2 = 0; h2 < 2; h2++) {
        const int row = brow + wm * 64 + mf * 16 + qr + 8 * h2;
#pragma unroll
        for (int nf = 0; nf < 4; nf++) {
            const int col = bcol + wn * 32 + nf * 8 + qc;
            const size_t ix = (size_t)row * N + col;
            float2 bb = *reinterpret_cast<const float2*>(bias + col);
            float m0  = acc[mf][nf][2 * h2 + 0] + bb.x;
            float m1v = acc[mf][nf][2 * h2 + 1] + bb.y;
            const bool sp0 = m0 > THRV, sp1 = m1v > THRV;
            *reinterpret_cast<float2*>(mem + ix) = make_float2(m0, m1v);
            uint32_t sv = (sp0 ? 0x1000u : 0u) | (sp1 ? 0x10000000u : 0u);
            *reinterpret_cast<uint32_t*>(spk + ix) = sv;
        }
    }
}

// ---------------------------------------------------------------------------
// Fused prep: weight/x splits + scheduler reset (ticket + counters).
// ---------------------------------------------------------------------------
#define N_W1 (DIM_H1 * DIM_D)
#define N_W2 (DIM_H2 * DIM_H1)
#define N_X  (BATCH * DIM_D)

__global__ void __launch_bounds__(256)
prep_all(const float* __restrict__ W1, const float* __restrict__ W2,
         const float* __restrict__ x,
         __half* __restrict__ w1h, __half* __restrict__ w1l,
         __half* __restrict__ w1hu,
         __half* __restrict__ w2h, __half* __restrict__ w2l,
         __half* __restrict__ xh, __half* __restrict__ xl,
         __half* __restrict__ xhs)
{
    // scheduler reset (block 0)
    if (blockIdx.x == 0) {
        for (int z = threadIdx.x; z < NUM_STEPS * RB_COUNT; z += 256) {
            (&g_cnt1[0][0])[z] = 0u;
            (&g_cnt2[0][0])[z] = 0u;
        }
        if (threadIdx.x == 0) g_ticket = 0u;
    }
    const int total = N_W1 + N_W2 + N_X;
    for (int i = blockIdx.x * 256 + threadIdx.x; i < total; i += gridDim.x * 256) {
        if (i < N_W1) {
            float v = W1[i] * 2048.0f;
            __half h = __float2half_rn(v);
            w1h[i] = h;
            w1l[i] = __float2half_rn(v - __half2float(h));
            w1hu[i] = __float2half_rn(__half2float(h) * (1.0f / 2048.0f));
        } else if (i < N_W1 + N_W2) {
            int j = i - N_W1;
            float v = W2[j] * 2048.0f;
            __half h = __float2half_rn(v);
            w2h[j] = h;
            w2l[j] = __float2half_rn(v - __half2float(h));
        } else {
            int j = i - N_W1 - N_W2;
            float v = x[j];
            __half h = __float2half_rn(v);
            xh[j] = h;
            xl[j] = __float2half_rn(v - __half2float(h));
            xhs[j] = __float2half_rn(__half2float(h) * (1.0f / 2048.0f));
        }
    }
}

// ---------------------------------------------------------------------------
// Readout: out[b,c] = (spk_sum[b,:]/NUM_STEPS) . Wo[c,:] + bo[c]
// ---------------------------------------------------------------------------
__global__ void __launch_bounds__(256)
snn_readout(const __half* __restrict__ spk_sum, const float* __restrict__ Wo,
            const float* __restrict__ bo, float* __restrict__ out)
{
    const int c  = threadIdx.x & 63;
    const int r4 = threadIdx.x >> 6;
    const size_t b = (size_t)blockIdx.x * 4 + r4;
    const __half* s = spk_sum + b * DIM_H2;
    const float* w = Wo + (size_t)c * DIM_H2;
    float acc = 0.0f;
#pragma unroll 4
    for (int k = 0; k < DIM_H2; k += 4) {
        __half2 s01 = *reinterpret_cast<const __half2*>(s + k);
        __half2 s23 = *reinterpret_cast<const __half2*>(s + k + 2);
        float2 f01 = __half22float2(s01);
        float2 f23 = __half22float2(s23);
        float4 wv = *reinterpret_cast<const float4*>(w + k);
        acc = fmaf(f01.x, wv.x, acc);
        acc = fmaf(f01.y, wv.y, acc);
        acc = fmaf(f23.x, wv.z, acc);
        acc = fmaf(f23.y, wv.w, acc);
    }
    out[b * DIM_C + c] = acc * (1.0f / (float)NUM_STEPS) + bo[c];
}

// ---------------------------------------------------------------------------
extern "C" void kernel_launch(void* const* d_in, const int* in_sizes, int n_in,
                              void* d_out, int out_size)
{
    const float* x  = (const float*)d_in[0];
    const float* W1 = (const float*)d_in[1];
    const float* b1 = (const float*)d_in[2];
    const float* W2 = (const float*)d_in[3];
    const float* b2 = (const float*)d_in[4];
    const float* Wo = (const float*)d_in[5];
    const float* bo = (const float*)d_in[6];
    float* out = (float*)d_out;

    auto sym = [](const void* s) { void* p; cudaGetSymbolAddress(&p, s); return p; };
    float*  m1   = (float*)sym(g_m1);
    float*  m2   = (float*)sym(g_m2);
    __half* spk  = (__half*)sym(g_spk);
    __half* s1   = (__half*)sym(g_s1);
    __half* s2   = (__half*)sym(g_s2);
    __half* w1h  = (__half*)sym(g_w1h);
    __half* w1l  = (__half*)sym(g_w1l);
    __half* w1hu = (__half*)sym(g_w1hu);
    __half* w2h  = (__half*)sym(g_w2h);
    __half* w2l  = (__half*)sym(g_w2l);
    __half* xh   = (__half*)sym(g_xh);
    __half* xl   = (__half*)sym(g_xl);
    __half* xhs  = (__half*)sym(g_xhs);

    constexpr int SM_PS = 1024 + 2 * 3 * 16384;   //  99328 B -> 2 CTA/SM
    constexpr int SM_TZ = 2 * 5 * 16384;          // 163840 B -> 1 CTA/SM
    cudaFuncSetAttribute(snn_tz, cudaFuncAttributeMaxDynamicSharedMemorySize, SM_TZ);
    cudaFuncSetAttribute(snn_persist, cudaFuncAttributeMaxDynamicSharedMemorySize, SM_PS);

    // Full-residency grid (deadlock-free requires grid <= resident capacity)
    int nsm = 0, occ = 0;
    cudaDeviceGetAttribute(&nsm, cudaDevAttrMultiProcessorCount, 0);
    cudaOccupancyMaxActiveBlocksPerMultiprocessor(&occ, snn_persist, 256, SM_PS);
    if (occ < 1) occ = 1;
    if (occ > 2) occ = 2;
    const int pgrid = nsm * occ;

    prep_all<<<2048, 256>>>(W1, W2, x, w1h, w1l, w1hu, w2h, w2l, xh, xl, xhs);

    dim3 gtz(DIM_H1 / 128, BATCH / 128);   // (16, 32)
    snn_tz<<<gtz, 256, SM_TZ>>>(xh, xhs, xl, w1hu, w1l, b1, m1, s1, DIM_H1, DIM_D);

    snn_persist<<<pgrid, 256, SM_PS>>>(w1h, w1l, w2h, w2l, b1, b2,
                                       m1, m2, s1, s2, spk);

    snn_readout<<<BATCH / 4, 256>>>(spk, Wo, bo, out);
}

// round 10
// speedup vs baseline: 2.2827x; 1.0470x over previous
#include <cuda_runtime.h>
#include <cuda_fp16.h>
#include <cstdint>

// ===========================================================================
// SNN (20 steps, 2 fused Linear+LIF + feedback) on mma.sync (HMMA).
// Spikes = exactly 2^-11 in fp16; weights split into 2 fp16 limbs scaled by
// 2^11 -> products exact, residual ~|w|*2^-24 (fp32-identical trajectory).
// Round 10: round-9 persistent dataflow kernel (proven 4606us) + tiled smem
// readout GEMM (replaces the 261us strided-load readout).
// ===========================================================================

#define BATCH   4096
#define DIM_D   1024
#define DIM_H1  2048
#define DIM_H2  1024
#define DIM_C   64
#define NUM_STEPS 20
#define BETA 0.9f
#define THRV 1.0f

#define RB_COUNT 32                 // 4096/128 row blocks
#define L1_CB 16                    // 2048/128
#define L2_CB 8                     // 1024/128
#define TILES_PER_STEP (RB_COUNT * (L1_CB + L2_CB))        // 768
#define TOT_TILES (RB_COUNT * L2_CB + (NUM_STEPS - 1) * TILES_PER_STEP)  // 14848

// ---------------------------------------------------------------------------
// Device-global state / scratch
// ---------------------------------------------------------------------------
__device__ float  g_m1 [(size_t)BATCH * DIM_H1];
__device__ float  g_m2 [(size_t)BATCH * DIM_H2];
__device__ __half g_spk[(size_t)BATCH * DIM_H2];    // spike counts (fp16 ints)
__device__ __half g_s1 [(size_t)BATCH * DIM_H1];
__device__ __half g_s2 [(size_t)BATCH * DIM_H2];
__device__ __half g_w1h [(size_t)DIM_H1 * DIM_D];
__device__ __half g_w1l [(size_t)DIM_H1 * DIM_D];
__device__ __half g_w1hu[(size_t)DIM_H1 * DIM_D];
__device__ __half g_w2h [(size_t)DIM_H2 * DIM_H1];
__device__ __half g_w2l [(size_t)DIM_H2 * DIM_H1];
__device__ __half g_xh  [(size_t)BATCH * DIM_D];
__device__ __half g_xl  [(size_t)BATCH * DIM_D];
__device__ __half g_xhs [(size_t)BATCH * DIM_D];
// Scheduler state (zeroed by prep_all each launch)
__device__ unsigned g_ticket;
__device__ unsigned g_cnt1[NUM_STEPS][RB_COUNT];
__device__ unsigned g_cnt2[NUM_STEPS][RB_COUNT];

// ---------------------------------------------------------------------------
// PTX helpers
// ---------------------------------------------------------------------------
__device__ __forceinline__ uint32_t smem_u32(const void* p) {
    uint32_t a;
    asm("{ .reg .u64 t; cvta.to.shared.u64 t, %1; cvt.u32.u64 %0, t; }"
        : "=r"(a) : "l"(p));
    return a;
}
__device__ __forceinline__ void cp16(uint32_t dst, const void* src) {
    asm volatile("cp.async.cg.shared.global [%0], [%1], 16;"
                 :: "r"(dst), "l"(__cvta_generic_to_global(src)) : "memory");
}
__device__ __forceinline__ void ldsm4(uint32_t addr, uint32_t& r0, uint32_t& r1,
                                      uint32_t& r2, uint32_t& r3) {
    asm volatile("ldmatrix.sync.aligned.m8n8.x4.shared.b16 {%0,%1,%2,%3}, [%4];"
                 : "=r"(r0), "=r"(r1), "=r"(r2), "=r"(r3) : "r"(addr));
}
__device__ __forceinline__ void mma16816(float* c, const uint32_t a[4],
                                         uint32_t b0, uint32_t b1) {
    asm volatile(
        "mma.sync.aligned.m16n8k16.row.col.f32.f16.f16.f32 "
        "{%0,%1,%2,%3}, {%4,%5,%6,%7}, {%8,%9}, {%0,%1,%2,%3};"
        : "+f"(c[0]), "+f"(c[1]), "+f"(c[2]), "+f"(c[3])
        : "r"(a[0]), "r"(a[1]), "r"(a[2]), "r"(a[3]), "r"(b0), "r"(b1));
}

// ===========================================================================
// Persistent steady-state kernel (unchanged from round 9).
// ===========================================================================
__global__ void __launch_bounds__(256, 2)
snn_persist(const __half* __restrict__ w1h, const __half* __restrict__ w1l,
            const __half* __restrict__ w2h, const __half* __restrict__ w2l,
            const float* __restrict__ b1, const float* __restrict__ b2,
            float* __restrict__ m1, float* __restrict__ m2,
            __half* __restrict__ s1, __half* __restrict__ s2,
            __half* __restrict__ spk_sum)
{
    constexpr int TILE = 16384;
    constexpr int STAGE = 3 * TILE;
    extern __shared__ char smem[];
    unsigned* shdr = reinterpret_cast<unsigned*>(smem);
    const uint32_t sb = smem_u32(smem) + 1024;

    const int tid = threadIdx.x, lane = tid & 31, wid = tid >> 5;
    const int wm = wid >> 2, wn = wid & 3;

    const int arow = (lane & 7) + 8 * ((lane >> 3) & 1);
    const int asel = lane >> 4;
    const int brw  = (lane & 7) + 8 * (lane >> 4);
    const int bsel = (lane >> 3) & 1;
    const int sx   = lane & 7;
    const int qr   = lane >> 2, qc = (lane & 3) * 2;

    for (;;) {
        __syncthreads();
        if (tid == 0) shdr[0] = atomicAdd(&g_ticket, 1u);
        __syncthreads();
        const unsigned ti = shdr[0];
        if (ti >= TOT_TILES) break;

        int t, layer, rb, cb;
        if (ti < RB_COUNT * L2_CB) {
            t = 0; layer = 2; rb = ti >> 3; cb = ti & 7;
        } else {
            const unsigned j = ti - RB_COUNT * L2_CB;
            t = 1 + (int)(j / TILES_PER_STEP);
            const unsigned r = j % TILES_PER_STEP;
            if (r < RB_COUNT * L1_CB) { layer = 1; rb = r >> 4; cb = r & 15; }
            else { const unsigned q = r - RB_COUNT * L1_CB; layer = 2; rb = q >> 3; cb = q & 7; }
        }

        if (tid == 0) {
            volatile unsigned* dep = nullptr;
            unsigned tgt = 0;
            if (layer == 1)      { dep = &g_cnt2[t - 1][rb]; tgt = L2_CB; }
            else if (t > 0)      { dep = &g_cnt1[t][rb];     tgt = L1_CB; }
            if (dep) while (*dep < tgt) __nanosleep(64);
        }
        __syncthreads();
        __threadfence();

        const int K = (layer == 1) ? DIM_H2 : DIM_H1;
        const int N = (layer == 1) ? DIM_H1 : DIM_H2;
        const __half* A  = (layer == 1) ? s2  : s1;
        const __half* W0 = (layer == 1) ? w1h : w2h;
        const __half* W1 = (layer == 1) ? w1l : w2l;
        const float* bias = (layer == 1) ? b1 : b2;
        float* mem = (layer == 1) ? m1 : m2;
        __half* spko = (layer == 1) ? s1 : s2;
        const bool SUMf = (layer == 2);
        const bool FIRSTf = (layer == 2) && (t == 0);
        const int brow = rb * 128, bcol = cb * 128;

        const __half* Ab = A + (size_t)brow * K;
        const __half* Wp0 = W0 + (size_t)bcol * K;
        const __half* Wp1 = W1 + (size_t)bcol * K;

        auto load_stage = [&](int st, int k0) {
            const uint32_t s0 = sb + st * STAGE;
            for (int q = tid; q < 1024; q += 256) {
                int r = q >> 3, c = q & 7;
                cp16(s0 + r * 128 + ((c ^ (r & 7)) << 4),
                     Ab + (size_t)r * K + k0 + c * 8);
            }
            for (int q = tid; q < 1024; q += 256) {
                int r = q >> 3, c = q & 7;
                cp16(s0 + TILE + r * 128 + ((c ^ (r & 7)) << 4),
                     Wp0 + (size_t)r * K + k0 + c * 8);
            }
            for (int q = tid; q < 1024; q += 256) {
                int r = q >> 3, c = q & 7;
                cp16(s0 + 2 * TILE + r * 128 + ((c ^ (r & 7)) << 4),
                     Wp1 + (size_t)r * K + k0 + c * 8);
            }
            asm volatile("cp.async.commit_group;" ::: "memory");
        };

        float acc[4][4][4];
#pragma unroll
        for (int i = 0; i < 4; i++)
#pragma unroll
            for (int j = 0; j < 4; j++)
#pragma unroll
                for (int k = 0; k < 4; k++) acc[i][j][k] = 0.0f;

        const int nch = K / 64;
        load_stage(0, 0);

        for (int ch = 0; ch < nch; ch++) {
            if (ch + 1 < nch) {
                load_stage((ch + 1) & 1, (ch + 1) * 64);
                asm volatile("cp.async.wait_group 1;" ::: "memory");
            } else {
                asm volatile("cp.async.wait_group 0;" ::: "memory");
            }
            __syncthreads();

            const uint32_t s0 = sb + (ch & 1) * STAGE;
            uint32_t bb[2][2];
#pragma unroll
            for (int w = 0; w < 2; w++)
#pragma unroll
                for (int h = 0; h < 2; h++)
                    bb[w][h] = s0 + (1 + w) * TILE + (wn * 32 + h * 16 + brw) * 128;

#pragma unroll
            for (int ks = 0; ks < 4; ks++) {
                uint32_t b[2][8];
#pragma unroll
                for (int w = 0; w < 2; w++) {
                    const uint32_t off = ((2 * ks + bsel) ^ sx) << 4;
                    ldsm4(bb[w][0] + off, b[w][0], b[w][1], b[w][2], b[w][3]);
                    ldsm4(bb[w][1] + off, b[w][4], b[w][5], b[w][6], b[w][7]);
                }
                const uint32_t aoff = ((2 * ks + asel) ^ sx) << 4;
                uint32_t a[4][4];
#pragma unroll
                for (int mf = 0; mf < 4; mf++)
                    ldsm4(s0 + (wm * 64 + mf * 16 + arow) * 128 + aoff,
                          a[mf][0], a[mf][1], a[mf][2], a[mf][3]);
#pragma unroll
                for (int w = 0; w < 2; w++)
#pragma unroll
                    for (int mf = 0; mf < 4; mf++)
#pragma unroll
                        for (int nf = 0; nf < 4; nf++)
                            mma16816(acc[mf][nf], a[mf], b[w][2 * nf], b[w][2 * nf + 1]);
            }
            __syncthreads();
        }

#pragma unroll
        for (int mf = 0; mf < 4; mf++)
#pragma unroll
        for (int h = 0; h < 2; h++) {
            const int row = brow + wm * 64 + mf * 16 + qr + 8 * h;
#pragma unroll
            for (int nf = 0; nf < 4; nf++) {
                const int col = bcol + wn * 32 + nf * 8 + qc;
                const size_t ix = (size_t)row * N + col;
                float2 bb = *reinterpret_cast<const float2*>(bias + col);
                float v0 = acc[mf][nf][2 * h + 0] + bb.x;
                float v1 = acc[mf][nf][2 * h + 1] + bb.y;
                float m0, m1v;
                if (FIRSTf) {
                    m0 = v0; m1v = v1;
                } else {
                    float2 mo = *reinterpret_cast<const float2*>(mem + ix);
                    m0  = BETA * mo.x + v0 - ((mo.x > THRV) ? THRV : 0.0f);
                    m1v = BETA * mo.y + v1 - ((mo.y > THRV) ? THRV : 0.0f);
                }
                const bool sp0 = m0 > THRV, sp1 = m1v > THRV;
                *reinterpret_cast<float2*>(mem + ix) = make_float2(m0, m1v);
                uint32_t sv = (sp0 ? 0x1000u : 0u) | (sp1 ? 0x10000000u : 0u);
                *reinterpret_cast<uint32_t*>(spko + ix) = sv;
                if (SUMf) {
                    __half2 add = __floats2half2_rn(sp0 ? 1.0f : 0.0f,
                                                    sp1 ? 1.0f : 0.0f);
                    __half2* ss = reinterpret_cast<__half2*>(spk_sum + ix);
                    if (FIRSTf) *ss = add;
                    else        *ss = __hadd2(*ss, add);
                }
            }
        }

        __threadfence();
        __syncthreads();
        if (tid == 0) {
            unsigned* rel = (layer == 1) ? &g_cnt1[t][rb] : &g_cnt2[t][rb];
            atomicAdd(rel, 1u);
        }
    }
}

// ===========================================================================
// t=0 layer-1 kernel (real-valued x, 3 fp16 limb products). Runs once.
// ===========================================================================
__global__ void __launch_bounds__(256, 2)
snn_tz(const __half* __restrict__ A0, const __half* __restrict__ A1,
       const __half* __restrict__ A2,
       const __half* __restrict__ W0, const __half* __restrict__ W1,
       const float* __restrict__ bias, float* __restrict__ mem,
       __half* __restrict__ spk, int N, int K)
{
    constexpr int FT = 16384;
    constexpr int FSTAGE = 5 * FT;
    extern __shared__ char smem[];
    const uint32_t sb = smem_u32(smem);

    const int tid = threadIdx.x, lane = tid & 31, wid = tid >> 5;
    const int wm = wid >> 2, wn = wid & 3;
    const int brow = blockIdx.y * 128, bcol = blockIdx.x * 128;

    const __half* Ap[3] = { A0 + (size_t)brow * K, A1 + (size_t)brow * K,
                            A2 + (size_t)brow * K };
    const __half* Wp[2] = { W0 + (size_t)bcol * K, W1 + (size_t)bcol * K };

    auto load_stage = [&](int st, int k0) {
        const uint32_t s0 = sb + st * FSTAGE;
#pragma unroll
        for (int l = 0; l < 3; l++) {
            const uint32_t d = s0 + l * FT;
            for (int q = tid; q < 1024; q += 256) {
                int r = q >> 3, c = q & 7;
                cp16(d + r * 128 + ((c ^ (r & 7)) << 4),
                     Ap[l] + (size_t)r * K + k0 + c * 8);
            }
        }
#pragma unroll
        for (int l = 0; l < 2; l++) {
            const uint32_t d = s0 + (3 + l) * FT;
            for (int q = tid; q < 1024; q += 256) {
                int r = q >> 3, c = q & 7;
                cp16(d + r * 128 + ((c ^ (r & 7)) << 4),
                     Wp[l] + (size_t)r * K + k0 + c * 8);
            }
        }
        asm volatile("cp.async.commit_group;" ::: "memory");
    };

    const int arow = (lane & 7) + 8 * ((lane >> 3) & 1);
    const int asel = lane >> 4;
    const int brw  = (lane & 7) + 8 * (lane >> 4);
    const int bsel = (lane >> 3) & 1;
    const int sx   = lane & 7;

    float acc[4][4][4];
#pragma unroll
    for (int i = 0; i < 4; i++)
#pragma unroll
        for (int j = 0; j < 4; j++)
#pragma unroll
            for (int k = 0; k < 4; k++) acc[i][j][k] = 0.0f;

    const int nch = K / 64;
    load_stage(0, 0);

    for (int ch = 0; ch < nch; ch++) {
        asm volatile("cp.async.wait_group 0;" ::: "memory");
        __syncthreads();
        if (ch + 1 < nch) load_stage((ch + 1) & 1, (ch + 1) * 64);

        const uint32_t s0 = sb + (ch & 1) * FSTAGE;
#pragma unroll
        for (int ks = 0; ks < 4; ks++) {
            const uint32_t aoff = ((2 * ks + asel) ^ sx) << 4;
            const uint32_t boff = ((2 * ks + bsel) ^ sx) << 4;
            uint32_t b[2][8];
#pragma unroll
            for (int w = 0; w < 2; w++) {
                const uint32_t bw = s0 + (3 + w) * FT + (wn * 32 + brw) * 128 + boff;
                ldsm4(bw, b[w][0], b[w][1], b[w][2], b[w][3]);
                ldsm4(bw + 16 * 128, b[w][4], b[w][5], b[w][6], b[w][7]);
            }
            const int PA[3] = {0, 1, 2}, PW[3] = {0, 1, 0};
#pragma unroll
            for (int p = 0; p < 3; p++) {
                uint32_t a[4][4];
#pragma unroll
                for (int mf = 0; mf < 4; mf++)
                    ldsm4(s0 + PA[p] * FT + (wm * 64 + mf * 16 + arow) * 128 + aoff,
                          a[mf][0], a[mf][1], a[mf][2], a[mf][3]);
#pragma unroll
                for (int mf = 0; mf < 4; mf++)
#pragma unroll
                    for (int nf = 0; nf < 4; nf++)
                        mma16816(acc[mf][nf], a[mf], b[PW[p]][2 * nf], b[PW[p]][2 * nf + 1]);
            }
        }
        __syncthreads();
    }

    const int qr = lane >> 2, qc = (lane & 3) * 2;
#pragma unroll
    for (int mf = 0; mf < 4; mf++)
#pragma unroll
    for (int h2 = 0; h2 < 2; h2++) {
        const int row = brow + wm * 64 + mf * 16 + qr + 8 * h2;
#pragma unroll
        for (int nf = 0; nf < 4; nf++) {
            const int col = bcol + wn * 32 + nf * 8 + qc;
            const size_t ix = (size_t)row * N + col;
            float2 bb = *reinterpret_cast<const float2*>(bias + col);
            float m0  = acc[mf][nf][2 * h2 + 0] + bb.x;
            float m1v = acc[mf][nf][2 * h2 + 1] + bb.y;
            const bool sp0 = m0 > THRV, sp1 = m1v > THRV;
            *reinterpret_cast<float2*>(mem + ix) = make_float2(m0, m1v);
            uint32_t sv = (sp0 ? 0x1000u : 0u) | (sp1 ? 0x10000000u : 0u);
            *reinterpret_cast<uint32_t*>(spk + ix) = sv;
        }
    }
}

// ---------------------------------------------------------------------------
// Fused prep: weight/x splits + scheduler reset.
// ---------------------------------------------------------------------------
#define N_W1 (DIM_H1 * DIM_D)
#define N_W2 (DIM_H2 * DIM_H1)
#define N_X  (BATCH * DIM_D)

__global__ void __launch_bounds__(256)
prep_all(const float* __restrict__ W1, const float* __restrict__ W2,
         const float* __restrict__ x,
         __half* __restrict__ w1h, __half* __restrict__ w1l,
         __half* __restrict__ w1hu,
         __half* __restrict__ w2h, __half* __restrict__ w2l,
         __half* __restrict__ xh, __half* __restrict__ xl,
         __half* __restrict__ xhs)
{
    if (blockIdx.x == 0) {
        for (int z = threadIdx.x; z < NUM_STEPS * RB_COUNT; z += 256) {
            (&g_cnt1[0][0])[z] = 0u;
            (&g_cnt2[0][0])[z] = 0u;
        }
        if (threadIdx.x == 0) g_ticket = 0u;
    }
    const int total = N_W1 + N_W2 + N_X;
    for (int i = blockIdx.x * 256 + threadIdx.x; i < total; i += gridDim.x * 256) {
        if (i < N_W1) {
            float v = W1[i] * 2048.0f;
            __half h = __float2half_rn(v);
            w1h[i] = h;
            w1l[i] = __float2half_rn(v - __half2float(h));
            w1hu[i] = __float2half_rn(__half2float(h) * (1.0f / 2048.0f));
        } else if (i < N_W1 + N_W2) {
            int j = i - N_W1;
            float v = W2[j] * 2048.0f;
            __half h = __float2half_rn(v);
            w2h[j] = h;
            w2l[j] = __float2half_rn(v - __half2float(h));
        } else {
            int j = i - N_W1 - N_W2;
            float v = x[j];
            __half h = __float2half_rn(v);
            xh[j] = h;
            xl[j] = __float2half_rn(v - __half2float(h));
            xhs[j] = __float2half_rn(__half2float(h) * (1.0f / 2048.0f));
        }
    }
}

// ---------------------------------------------------------------------------
// Readout (tiled smem GEMM): out[b,c] = (spk_sum[b,:]/20) . Wo[c,:] + bo[c]
// Block = 64 batch rows x 64 cols; K chunks of 128 staged k-major in smem.
// Per-output accumulation is k-ascending in one fp32 acc -> bit-identical
// to the previous readout.
// ---------------------------------------------------------------------------
__global__ void __launch_bounds__(256)
snn_readout(const __half* __restrict__ spk_sum, const float* __restrict__ Wo,
            const float* __restrict__ bo, float* __restrict__ out)
{
    extern __shared__ float rsm[];              // s_sm[128][64] + w_sm[128][64]
    float* s_sm = rsm;
    float* w_sm = rsm + 128 * 64;

    const int tid = threadIdx.x;
    const int tr = tid & 15, tc = tid >> 4;     // 16 x 16 thread grid
    const int r0 = tr * 4, c0 = tc * 4;
    const int rowbase = blockIdx.x * 64;

    float acc[4][4];
#pragma unroll
    for (int i = 0; i < 4; i++)
#pragma unroll
        for (int j = 0; j < 4; j++) acc[i][j] = 0.0f;

    for (int kc = 0; kc < DIM_H2 / 128; kc++) {
        const int k0 = kc * 128;
        // s chunk: 64 rows x 128 k (fp16) -> s_sm[k][r] (fp32), conflict-free STS
#pragma unroll
        for (int i = 0; i < 4; i++) {
            int q = i * 256 + tid;              // 0..1023
            int r = q & 63, kg = q >> 6;        // kg: 0..15 (8 halfs each)
            uint4 v = *reinterpret_cast<const uint4*>(
                spk_sum + (size_t)(rowbase + r) * DIM_H2 + k0 + kg * 8);
            const __half2* h2 = reinterpret_cast<const __half2*>(&v);
#pragma unroll
            for (int t = 0; t < 4; t++) {
                float2 f = __half22float2(h2[t]);
                s_sm[(kg * 8 + 2 * t + 0) * 64 + r] = f.x;
                s_sm[(kg * 8 + 2 * t + 1) * 64 + r] = f.y;
            }
        }
        // w chunk: 64 c x 128 k (fp32) -> w_sm[k][c], conflict-free STS
#pragma unroll
        for (int i = 0; i < 8; i++) {
            int q = i * 256 + tid;              // 0..2047
            int c = q & 63, kq = q >> 6;        // kq: 0..31 (4 floats each)
            float4 v = *reinterpret_cast<const float4*>(
                Wo + (size_t)c * DIM_H2 + k0 + kq * 4);
            w_sm[(kq * 4 + 0) * 64 + c] = v.x;
            w_sm[(kq * 4 + 1) * 64 + c] = v.y;
            w_sm[(kq * 4 + 2) * 64 + c] = v.z;
            w_sm[(kq * 4 + 3) * 64 + c] = v.w;
        }
        __syncthreads();

#pragma unroll 8
        for (int k = 0; k < 128; k++) {
            float4 sv = *reinterpret_cast<const float4*>(s_sm + k * 64 + r0);
            float4 wv = *reinterpret_cast<const float4*>(w_sm + k * 64 + c0);
            float s4[4] = {sv.x, sv.y, sv.z, sv.w};
            float w4[4] = {wv.x, wv.y, wv.z, wv.w};
#pragma unroll
            for (int i = 0; i < 4; i++)
#pragma unroll
                for (int j = 0; j < 4; j++)
                    acc[i][j] = fmaf(s4[i], w4[j], acc[i][j]);
        }
        __syncthreads();
    }

#pragma unroll
    for (int i = 0; i < 4; i++) {
        float4 o;
        o.x = acc[i][0] * (1.0f / NUM_STEPS) + bo[c0 + 0];
        o.y = acc[i][1] * (1.0f / NUM_STEPS) + bo[c0 + 1];
        o.z = acc[i][2] * (1.0f / NUM_STEPS) + bo[c0 + 2];
        o.w = acc[i][3] * (1.0f / NUM_STEPS) + bo[c0 + 3];
        *reinterpret_cast<float4*>(out + (size_t)(rowbase + r0 + i) * DIM_C + c0) = o;
    }
}

// ---------------------------------------------------------------------------
extern "C" void kernel_launch(void* const* d_in, const int* in_sizes, int n_in,
                              void* d_out, int out_size)
{
    const float* x  = (const float*)d_in[0];
    const float* W1 = (const float*)d_in[1];
    const float* b1 = (const float*)d_in[2];
    const float* W2 = (const float*)d_in[3];
    const float* b2 = (const float*)d_in[4];
    const float* Wo = (const float*)d_in[5];
    const float* bo = (const float*)d_in[6];
    float* out = (float*)d_out;

    auto sym = [](const void* s) { void* p; cudaGetSymbolAddress(&p, s); return p; };
    float*  m1   = (float*)sym(g_m1);
    float*  m2   = (float*)sym(g_m2);
    __half* spk  = (__half*)sym(g_spk);
    __half* s1   = (__half*)sym(g_s1);
    __half* s2   = (__half*)sym(g_s2);
    __half* w1h  = (__half*)sym(g_w1h);
    __half* w1l  = (__half*)sym(g_w1l);
    __half* w1hu = (__half*)sym(g_w1hu);
    __half* w2h  = (__half*)sym(g_w2h);
    __half* w2l  = (__half*)sym(g_w2l);
    __half* xh   = (__half*)sym(g_xh);
    __half* xl   = (__half*)sym(g_xl);
    __half* xhs  = (__half*)sym(g_xhs);

    constexpr int SM_PS = 1024 + 2 * 3 * 16384;   //  99328 -> 2 CTA/SM
    constexpr int SM_TZ = 2 * 5 * 16384;          // 163840 -> 1 CTA/SM
    constexpr int SM_RO = 2 * 128 * 64 * 4;       //  65536
    cudaFuncSetAttribute(snn_tz, cudaFuncAttributeMaxDynamicSharedMemorySize, SM_TZ);
    cudaFuncSetAttribute(snn_persist, cudaFuncAttributeMaxDynamicSharedMemorySize, SM_PS);
    cudaFuncSetAttribute(snn_readout, cudaFuncAttributeMaxDynamicSharedMemorySize, SM_RO);

    int nsm = 0, occ = 0;
    cudaDeviceGetAttribute(&nsm, cudaDevAttrMultiProcessorCount, 0);
    cudaOccupancyMaxActiveBlocksPerMultiprocessor(&occ, snn_persist, 256, SM_PS);
    if (occ < 1) occ = 1;
    if (occ > 2) occ = 2;
    const int pgrid = nsm * occ;

    prep_all<<<2048, 256>>>(W1, W2, x, w1h, w1l, w1hu, w2h, w2l, xh, xl, xhs);

    dim3 gtz(DIM_H1 / 128, BATCH / 128);
    snn_tz<<<gtz, 256, SM_TZ>>>(xh, xhs, xl, w1hu, w1l, b1, m1, s1, DIM_H1, DIM_D);

    snn_persist<<<pgrid, 256, SM_PS>>>(w1h, w1l, w2h, w2l, b1, b2,
                                       m1, m2, s1, s2, spk);

    snn_readout<<<BATCH / 64, 256, SM_RO>>>(spk, Wo, bo, out);
}